// round 17
// baseline (speedup 1.0000x reference)
#include <cuda_runtime.h>
#include <cooperative_groups.h>
#include <cstdint>
#include <cstddef>

namespace cg = cooperative_groups;
typedef unsigned long long ull;

// ---------------------------------------------------------------------------
// Problem constants (fixed by setup_inputs)
// ---------------------------------------------------------------------------
constexpr int B  = 4;
constexpr int N  = 16384;
constexpr int C  = 16;
constexpr int S  = 1024;       // npoint
constexpr int NS = 64;         // NSAMPLE
constexpr int NG = B * S;                 // 4096 groups
constexpr int M  = NG * NS;               // 262144 columns
constexpr int CIN1 = 3 + C;               // 19
constexpr int GB = M / 128;               // 2048 gemm blocks

// FPS cluster decomposition (8 CTAs x 256 threads per batch)
constexpr int CL      = 8;
constexpr int FPS_T   = 256;
constexpr int PPT     = N / CL / FPS_T;   // 8 points per thread
constexpr int SLICE   = N / CL;           // 2048 points per CTA
constexpr int NW      = FPS_T / 32;       // 8 warps

// Output layout: new_xyz (B,S,3) | new_features (B,128,S) | inds (B,S), all f32
constexpr int OUT_FEAT = B * S * 3;              // 12288
constexpr int OUT_INDS = OUT_FEAT + B * 128 * S; // 536576

// ---------------------------------------------------------------------------
// Scratch (device globals; no runtime allocation allowed)
// ---------------------------------------------------------------------------
__device__ float g_newxyz[NG * 3];
__device__ float g_X0[(size_t)CIN1 * M];     // ~20 MB
__device__ float g_Y2[(size_t)64 * M];       // 67 MB
__device__ float g_max3[(size_t)128 * NG];   // 2 MB
__device__ float g_part[(size_t)128 * GB * 2];
__device__ float g_scl1[64],  g_shf1[64];
__device__ float g_scl2[64],  g_shf2[64];

// ---------------------------------------------------------------------------
// DSMEM / packed-f32 primitives
// ---------------------------------------------------------------------------
__device__ __forceinline__ uint32_t mapa_sh(uint32_t local, uint32_t rank) {
    uint32_t r;
    asm("mapa.shared::cluster.u32 %0, %1, %2;" : "=r"(r) : "r"(local), "r"(rank));
    return r;
}
__device__ __forceinline__ void st_cluster_u64(uint32_t addr, ull v) {
    asm volatile("st.shared::cluster.u64 [%0], %1;" :: "r"(addr), "l"(v) : "memory");
}
__device__ __forceinline__ void st_cluster_v4(uint32_t addr, uint32_t a, uint32_t b2,
                                              uint32_t c2, uint32_t d2) {
    asm volatile("st.shared::cluster.v4.b32 [%0], {%1,%2,%3,%4};"
                 :: "r"(addr), "r"(a), "r"(b2), "r"(c2), "r"(d2) : "memory");
}
__device__ __forceinline__ ull packf2(float lo, float hi) {
    ull r; asm("mov.b64 %0, {%1, %2};" : "=l"(r) : "f"(lo), "f"(hi)); return r;
}
__device__ __forceinline__ void unpackf2(ull v, float& lo, float& hi) {
    asm("mov.b64 {%0, %1}, %2;" : "=f"(lo), "=f"(hi) : "l"(v));
}
__device__ __forceinline__ ull addx2(ull a, ull b) {
    ull r; asm("add.rn.f32x2 %0, %1, %2;" : "=l"(r) : "l"(a), "l"(b)); return r;
}
__device__ __forceinline__ ull mulx2(ull a, ull b) {
    ull r; asm("mul.rn.f32x2 %0, %1, %2;" : "=l"(r) : "l"(a), "l"(b)); return r;
}

// ---------------------------------------------------------------------------
// 1) Furthest point sampling — R16 exchange structure (hierarchical + 
//    cluster.sync), with packed-f32x2 distance math and a select-free
//    REDUX argmax (max tree + eligibility ffs + reduce_min index).
//    Bit-identical trajectory: same rn arithmetic, same first-occurrence
//    tie-break (min global index among max-distance points).
// ---------------------------------------------------------------------------
__global__ void __launch_bounds__(FPS_T, 1) __cluster_dims__(CL, 1, 1)
fps_kernel(const float* __restrict__ xyz, float* __restrict__ out)
{
    __shared__ ull    wkey[NW];
    __shared__ float4 wxyz[NW];
    __shared__ ull    skey[2][CL];
    __shared__ float4 sxyz[2][CL];

    cg::cluster_group cluster = cg::this_cluster();
    const unsigned rank = cluster.block_rank();
    const int b = blockIdx.x >> 3;
    const float* __restrict__ p = xyz + (size_t)b * N * 3;
    const int t = threadIdx.x;
    const int lane = t & 31, wid = t >> 5;
    const int jbase = rank * SLICE + t;

    // pair m holds slots k=2m (lo) and k=2m+1 (hi); slot k is point jbase+k*256
    ull X2[4], Y2[4], Z2[4];
    float D[PPT];
#pragma unroll
    for (int m = 0; m < 4; m++) {
        int j0 = jbase + (2 * m) * FPS_T;
        int j1 = jbase + (2 * m + 1) * FPS_T;
        X2[m] = packf2(p[3 * j0],     p[3 * j1]);
        Y2[m] = packf2(p[3 * j0 + 1], p[3 * j1 + 1]);
        Z2[m] = packf2(p[3 * j0 + 2], p[3 * j1 + 2]);
        D[2 * m] = 1e10f;
        D[2 * m + 1] = 1e10f;
    }

    uint32_t ak0 = 0, ak1 = 0, ax0 = 0, ax1 = 0;
    if (wid == 0) {
        uint32_t k0 = (uint32_t)__cvta_generic_to_shared(&skey[0][rank]);
        uint32_t k1 = (uint32_t)__cvta_generic_to_shared(&skey[1][rank]);
        uint32_t x0 = (uint32_t)__cvta_generic_to_shared(&sxyz[0][rank]);
        uint32_t x1 = (uint32_t)__cvta_generic_to_shared(&sxyz[1][rank]);
        uint32_t tr = (uint32_t)(lane & 7);
        ak0 = mapa_sh(k0, tr); ak1 = mapa_sh(k1, tr);
        ax0 = mapa_sh(x0, tr); ax1 = mapa_sh(x1, tr);
    }

    int far = 0;
    float cx = p[0], cy = p[1], cz = p[2];

    for (int i = 0; i < S; i++) {
        // outputs on warp 1 (all threads hold identical cx/cy/cz/far)
        if (rank == 0 && t == 32) {
            int gi = b * S + i;
            g_newxyz[3 * gi]     = cx;
            g_newxyz[3 * gi + 1] = cy;
            g_newxyz[3 * gi + 2] = cz;
            out[3 * gi]     = cx;
            out[3 * gi + 1] = cy;
            out[3 * gi + 2] = cz;
            out[OUT_INDS + gi] = (float)far;
        }

        // packed distance update: d = (dx*dx + dy*dy) + dz*dz, rn per lane
        ull ncx2 = packf2(-cx, -cx), ncy2 = packf2(-cy, -cy), ncz2 = packf2(-cz, -cz);
        float nd[PPT];
#pragma unroll
        for (int m = 0; m < 4; m++) {
            ull dx2 = addx2(X2[m], ncx2);
            ull dy2 = addx2(Y2[m], ncy2);
            ull dz2 = addx2(Z2[m], ncz2);
            ull s = addx2(addx2(mulx2(dx2, dx2), mulx2(dy2, dy2)), mulx2(dz2, dz2));
            float d0, d1;
            unpackf2(s, d0, d1);
            nd[2 * m]     = fminf(D[2 * m], d0);     D[2 * m]     = nd[2 * m];
            nd[2 * m + 1] = fminf(D[2 * m + 1], d1); D[2 * m + 1] = nd[2 * m + 1];
        }

        // per-thread value max (no index tracking)
        float mall = fmaxf(fmaxf(fmaxf(nd[0], nd[1]), fmaxf(nd[2], nd[3])),
                           fmaxf(fmaxf(nd[4], nd[5]), fmaxf(nd[6], nd[7])));
        unsigned H = __reduce_max_sync(0xffffffffu, __float_as_uint(mall));
        float Hf = __uint_as_float(H);

        // eligibility mask -> smallest eligible k -> exact min-index candidate
        unsigned e = 0;
#pragma unroll
        for (int k = 0; k < PPT; k++) e |= (nd[k] == Hf) ? (1u << k) : 0u;
        unsigned cand = e ? ((((unsigned)(__ffs(e) - 1)) << 8) | (unsigned)t)
                          : 0xFFFFFFFFu;
        unsigned Lc = __reduce_min_sync(0xffffffffu, cand);   // min (k<<8|t) == min j

        if (cand == Lc) {   // unique winner lane (cand encodes t)
            int kk = (int)(cand >> 8);
            int pr = kk >> 1, hf = kk & 1;
            ull xp = (pr == 0) ? X2[0] : (pr == 1) ? X2[1] : (pr == 2) ? X2[2] : X2[3];
            ull yp = (pr == 0) ? Y2[0] : (pr == 1) ? Y2[1] : (pr == 2) ? Y2[2] : Y2[3];
            ull zp = (pr == 0) ? Z2[0] : (pr == 1) ? Z2[1] : (pr == 2) ? Z2[2] : Z2[3];
            float xl, xh, yl, yh, zl, zh;
            unpackf2(xp, xl, xh);
            unpackf2(yp, yl, yh);
            unpackf2(zp, zl, zh);
            wkey[wid] = ((ull)H << 32) | (unsigned)(~Lc);   // ~Lc: max => min index
            wxyz[wid] = make_float4(hf ? xh : xl, hf ? yh : yl, hf ? zh : zl, 0.f);
        }
        __syncthreads();

        const int par = i & 1;
        if (wid == 0) {
            ull k2 = wkey[lane & 7];
            unsigned kh = (unsigned)(k2 >> 32);
            unsigned BH = __reduce_max_sync(0xffffffffu, kh);
            unsigned kl = (kh == BH) ? (unsigned)k2 : 0u;   // losers' 0 < any ~Lc
            unsigned BL = __reduce_max_sync(0xffffffffu, kl);
            ull BW = ((ull)BH << 32) | BL;
            unsigned bw = __ballot_sync(0xffffffffu, (lane < 8) && (k2 == BW));
            int ws = __ffs(bw) - 1;
            float4 wc = wxyz[ws];            // LDS broadcast
            int j = (int)rank * SLICE + (int)(~BL);   // ~BL == Lc_min == (k<<8)|t
            ull PK = ((ull)BH << 32) | (unsigned)(N - 1 - j);
            if (lane < CL) {
                st_cluster_u64(par ? ak1 : ak0, PK);
                st_cluster_v4(par ? ax1 : ax0, __float_as_uint(wc.x),
                              __float_as_uint(wc.y), __float_as_uint(wc.z), 0u);
            }
        }
        cluster.sync();

        // per-warp resolve over the 8 CTA-winner slots (unchanged)
        ull a = 0;
        if (lane < CL) a = skey[par][lane];
        unsigned ch = (unsigned)(a >> 32);
        unsigned RH = __reduce_max_sync(0xffffffffu, ch);
        unsigned cl2 = (ch == RH) ? (unsigned)a : 0u;
        unsigned RL = __reduce_max_sync(0xffffffffu, cl2);
        ull W = ((ull)RH << 32) | RL;
        unsigned bal2 = __ballot_sync(0xffffffffu, (lane < CL) && (a == W));
        int slot = __ffs(bal2) - 1;
        float4 cc = sxyz[par][slot];
        cx = cc.x; cy = cc.y; cz = cc.z;
        far = N - 1 - (int)RL;
    }
}

// ---------------------------------------------------------------------------
// 2) Fused ball query + grouping (R16 verbatim): one warp per center.
// ---------------------------------------------------------------------------
__global__ void __launch_bounds__(256)
ballgroup_kernel(const float* __restrict__ xyz, const float* __restrict__ feat)
{
    __shared__ int sidx[8][NS];

    int gw = (blockIdx.x * blockDim.x + threadIdx.x) >> 5;
    if (gw >= NG) return;
    int lane = threadIdx.x & 31;
    int w = (threadIdx.x >> 5) & 7;
    int b = gw >> 10;
    const float* __restrict__ p = xyz + (size_t)b * N * 3;
    float cx = g_newxyz[3 * gw], cy = g_newxyz[3 * gw + 1], cz = g_newxyz[3 * gw + 2];

    int cnt = 0, first = 0;
    for (int base = 0; base < N; base += 32) {
        int j = base + lane;
        float dx = __fadd_rn(p[3 * j],     -cx);
        float dy = __fadd_rn(p[3 * j + 1], -cy);
        float dz = __fadd_rn(p[3 * j + 2], -cz);
        float d  = __fadd_rn(__fadd_rn(__fmul_rn(dx, dx), __fmul_rn(dy, dy)),
                             __fmul_rn(dz, dz));
        bool hit = d < 0.16f;
        unsigned mask = __ballot_sync(0xffffffffu, hit);
        if (mask) {
            if (cnt == 0) first = base + __ffs(mask) - 1;
            int pos = cnt + __popc(mask & ((1u << lane) - 1u));
            if (hit && pos < NS) sidx[w][pos] = j;
            cnt += __popc(mask);
            if (cnt >= NS) break;
        }
    }
    for (int q = cnt + lane; q < NS; q += 32) sidx[w][q] = first;
    __syncwarp();

    const float* fb = feat + (size_t)b * C * N;
#pragma unroll
    for (int h = 0; h < 2; h++) {
        int q = lane + h * 32;
        int j = sidx[w][q];
        int m = gw * NS + q;
        const float* pj = p + 3 * j;
        g_X0[(size_t)0 * M + m] = (pj[0] - cx) * 2.5f;
        g_X0[(size_t)1 * M + m] = (pj[1] - cy) * 2.5f;
        g_X0[(size_t)2 * M + m] = (pj[2] - cz) * 2.5f;
#pragma unroll
        for (int c = 0; c < C; c++)
            g_X0[(size_t)(3 + c) * M + m] = fb[(size_t)c * N + j];
    }
}

// ---------------------------------------------------------------------------
// 4a) Pass 1: BN1 partials from X0 (no Y1 materialization).
// ---------------------------------------------------------------------------
__global__ void __launch_bounds__(256)
gemm_p1(const float* __restrict__ Wg)
{
    __shared__ float Ws[CIN1 * 64];
    __shared__ float Xs[CIN1 * 128];

    const int tid = threadIdx.x;
    const int m0  = blockIdx.x * 128;
    const int tx  = tid & 15, ty = tid >> 4;

    for (int i = tid; i < CIN1 * 64; i += 256) {
        int c = i >> 6, o = i & 63;
        Ws[i] = Wg[o * CIN1 + c];
    }
    for (int i = tid; i < CIN1 * 32; i += 256) {
        int r = i >> 5, c4 = i & 31;
        *reinterpret_cast<float4*>(Xs + r * 128 + c4 * 4) =
            *reinterpret_cast<const float4*>(g_X0 + (size_t)r * M + m0 + c4 * 4);
    }
    __syncthreads();

    float acc[4][8];
#pragma unroll
    for (int i = 0; i < 4; i++)
#pragma unroll
        for (int jj = 0; jj < 8; jj++) acc[i][jj] = 0.f;

#pragma unroll 4
    for (int k = 0; k < CIN1; k++) {
        float4 w4 = *reinterpret_cast<const float4*>(Ws + k * 64 + ty * 4);
        float4 xa = *reinterpret_cast<const float4*>(Xs + k * 128 + tx * 8);
        float4 xb = *reinterpret_cast<const float4*>(Xs + k * 128 + tx * 8 + 4);
        float wr[4] = {w4.x, w4.y, w4.z, w4.w};
        float xr[8] = {xa.x, xa.y, xa.z, xa.w, xb.x, xb.y, xb.z, xb.w};
#pragma unroll
        for (int i = 0; i < 4; i++)
#pragma unroll
            for (int jj = 0; jj < 8; jj++)
                acc[i][jj] = fmaf(wr[i], xr[jj], acc[i][jj]);
    }

#pragma unroll
    for (int i = 0; i < 4; i++) {
        float sm = 0.f, sq = 0.f;
#pragma unroll
        for (int jj = 0; jj < 8; jj++) {
            sm += acc[i][jj];
            sq += acc[i][jj] * acc[i][jj];
        }
#pragma unroll
        for (int o = 8; o > 0; o >>= 1) {
            sm += __shfl_xor_sync(0xffffffffu, sm, o);
            sq += __shfl_xor_sync(0xffffffffu, sq, o);
        }
        if (tx == 0) {
            int o = ty * 4 + i;
            g_part[((size_t)o * GB + blockIdx.x) * 2]     = sm;
            g_part[((size_t)o * GB + blockIdx.x) * 2 + 1] = sq;
        }
    }
}

// ---------------------------------------------------------------------------
// 4b) Pass 2: recompute Y1 tile from X0, BN1+ReLU in smem, GEMM -> Y2 + partials
// ---------------------------------------------------------------------------
constexpr int L2_SMEM = (CIN1 * 64 + 64 * 64 + CIN1 * 128 + 64 * 128) * 4;

__global__ void __launch_bounds__(256)
gemm_l2(const float* __restrict__ W1g, const float* __restrict__ W2g)
{
    extern __shared__ float sm_[];
    float* W1s = sm_;
    float* W2s = W1s + CIN1 * 64;
    float* X0s = W2s + 64 * 64;
    float* Y1s = X0s + CIN1 * 128;

    const int tid = threadIdx.x;
    const int m0  = blockIdx.x * 128;
    const int tx  = tid & 15, ty = tid >> 4;

    for (int i = tid; i < CIN1 * 64; i += 256) {
        int c = i >> 6, o = i & 63;
        W1s[i] = W1g[o * CIN1 + c];
    }
    for (int i = tid; i < 64 * 64; i += 256) {
        int k = i >> 6, o = i & 63;
        W2s[i] = W2g[o * 64 + k];
    }
    for (int i = tid; i < CIN1 * 32; i += 256) {
        int r = i >> 5, c4 = i & 31;
        *reinterpret_cast<float4*>(X0s + r * 128 + c4 * 4) =
            *reinterpret_cast<const float4*>(g_X0 + (size_t)r * M + m0 + c4 * 4);
    }
    __syncthreads();

    {
        float a1[4][8];
#pragma unroll
        for (int i = 0; i < 4; i++)
#pragma unroll
            for (int jj = 0; jj < 8; jj++) a1[i][jj] = 0.f;
#pragma unroll 4
        for (int c = 0; c < CIN1; c++) {
            float4 w4 = *reinterpret_cast<const float4*>(W1s + c * 64 + ty * 4);
            float4 xa = *reinterpret_cast<const float4*>(X0s + c * 128 + tx * 8);
            float4 xb = *reinterpret_cast<const float4*>(X0s + c * 128 + tx * 8 + 4);
            float wr[4] = {w4.x, w4.y, w4.z, w4.w};
            float xr[8] = {xa.x, xa.y, xa.z, xa.w, xb.x, xb.y, xb.z, xb.w};
#pragma unroll
            for (int i = 0; i < 4; i++)
#pragma unroll
                for (int jj = 0; jj < 8; jj++)
                    a1[i][jj] = fmaf(wr[i], xr[jj], a1[i][jj]);
        }
#pragma unroll
        for (int i = 0; i < 4; i++) {
            int o = ty * 4 + i;
            float sc = g_scl1[o], sh = g_shf1[o];
            float4 va, vb;
            va.x = fmaxf(fmaf(a1[i][0], sc, sh), 0.f);
            va.y = fmaxf(fmaf(a1[i][1], sc, sh), 0.f);
            va.z = fmaxf(fmaf(a1[i][2], sc, sh), 0.f);
            va.w = fmaxf(fmaf(a1[i][3], sc, sh), 0.f);
            vb.x = fmaxf(fmaf(a1[i][4], sc, sh), 0.f);
            vb.y = fmaxf(fmaf(a1[i][5], sc, sh), 0.f);
            vb.z = fmaxf(fmaf(a1[i][6], sc, sh), 0.f);
            vb.w = fmaxf(fmaf(a1[i][7], sc, sh), 0.f);
            *reinterpret_cast<float4*>(Y1s + o * 128 + tx * 8)     = va;
            *reinterpret_cast<float4*>(Y1s + o * 128 + tx * 8 + 4) = vb;
        }
    }
    __syncthreads();

    float acc[4][8];
#pragma unroll
    for (int i = 0; i < 4; i++)
#pragma unroll
        for (int jj = 0; jj < 8; jj++) acc[i][jj] = 0.f;

#pragma unroll 4
    for (int k = 0; k < 64; k++) {
        float4 w4 = *reinterpret_cast<const float4*>(W2s + k * 64 + ty * 4);
        float4 xa = *reinterpret_cast<const float4*>(Y1s + k * 128 + tx * 8);
        float4 xb = *reinterpret_cast<const float4*>(Y1s + k * 128 + tx * 8 + 4);
        float wr[4] = {w4.x, w4.y, w4.z, w4.w};
        float xr[8] = {xa.x, xa.y, xa.z, xa.w, xb.x, xb.y, xb.z, xb.w};
#pragma unroll
        for (int i = 0; i < 4; i++)
#pragma unroll
            for (int jj = 0; jj < 8; jj++)
                acc[i][jj] = fmaf(wr[i], xr[jj], acc[i][jj]);
    }

#pragma unroll
    for (int i = 0; i < 4; i++) {
        size_t off = (size_t)(ty * 4 + i) * M + m0 + tx * 8;
        *reinterpret_cast<float4*>(g_Y2 + off) =
            make_float4(acc[i][0], acc[i][1], acc[i][2], acc[i][3]);
        *reinterpret_cast<float4*>(g_Y2 + off + 4) =
            make_float4(acc[i][4], acc[i][5], acc[i][6], acc[i][7]);
    }

#pragma unroll
    for (int i = 0; i < 4; i++) {
        float sm = 0.f, sq = 0.f;
#pragma unroll
        for (int jj = 0; jj < 8; jj++) {
            sm += acc[i][jj];
            sq += acc[i][jj] * acc[i][jj];
        }
#pragma unroll
        for (int o = 8; o > 0; o >>= 1) {
            sm += __shfl_xor_sync(0xffffffffu, sm, o);
            sq += __shfl_xor_sync(0xffffffffu, sq, o);
        }
        if (tx == 0) {
            int o = ty * 4 + i;
            g_part[((size_t)o * GB + blockIdx.x) * 2]     = sm;
            g_part[((size_t)o * GB + blockIdx.x) * 2 + 1] = sq;
        }
    }
}

// ---------------------------------------------------------------------------
// 4c) Pass 3: merged 128-output GEMM, fused BN2+ReLU in, partials + group max
// ---------------------------------------------------------------------------
__global__ void __launch_bounds__(256)
gemm128_l3(const float* __restrict__ Wg)
{
    __shared__ float Ws[64 * 128];
    __shared__ float Xs[32 * 128];

    const int tid = threadIdx.x;
    const int m0  = blockIdx.x * 128;
    const int tx  = tid & 15, ty = tid >> 4;

    for (int i = tid; i < 64 * 128; i += 256) {
        int k = i >> 7, o = i & 127;
        Ws[i] = Wg[o * 64 + k];
    }

    float acc[8][8];
#pragma unroll
    for (int i = 0; i < 8; i++)
#pragma unroll
        for (int jj = 0; jj < 8; jj++) acc[i][jj] = 0.f;

    for (int k0 = 0; k0 < 64; k0 += 32) {
        __syncthreads();
        for (int i = tid; i < 32 * 32; i += 256) {
            int r = i >> 5, c4 = i & 31;
            float4 v = *reinterpret_cast<const float4*>(
                g_Y2 + (size_t)(k0 + r) * M + m0 + c4 * 4);
            float sc = g_scl2[k0 + r], sh = g_shf2[k0 + r];
            v.x = fmaxf(fmaf(v.x, sc, sh), 0.f);
            v.y = fmaxf(fmaf(v.y, sc, sh), 0.f);
            v.z = fmaxf(fmaf(v.z, sc, sh), 0.f);
            v.w = fmaxf(fmaf(v.w, sc, sh), 0.f);
            *reinterpret_cast<float4*>(Xs + r * 128 + c4 * 4) = v;
        }
        __syncthreads();
#pragma unroll 4
        for (int k = 0; k < 32; k++) {
            float4 wa = *reinterpret_cast<const float4*>(Ws + (k0 + k) * 128 + ty * 8);
            float4 wb = *reinterpret_cast<const float4*>(Ws + (k0 + k) * 128 + ty * 8 + 4);
            float4 xa = *reinterpret_cast<const float4*>(Xs + k * 128 + tx * 8);
            float4 xb = *reinterpret_cast<const float4*>(Xs + k * 128 + tx * 8 + 4);
            float wr[8] = {wa.x, wa.y, wa.z, wa.w, wb.x, wb.y, wb.z, wb.w};
            float xr[8] = {xa.x, xa.y, xa.z, xa.w, xb.x, xb.y, xb.z, xb.w};
#pragma unroll
            for (int i = 0; i < 8; i++)
#pragma unroll
                for (int jj = 0; jj < 8; jj++)
                    acc[i][jj] = fmaf(wr[i], xr[jj], acc[i][jj]);
        }
    }

#pragma unroll
    for (int i = 0; i < 8; i++) {
        float sm = 0.f, sq = 0.f;
#pragma unroll
        for (int jj = 0; jj < 8; jj++) {
            sm += acc[i][jj];
            sq += acc[i][jj] * acc[i][jj];
        }
#pragma unroll
        for (int o = 8; o > 0; o >>= 1) {
            sm += __shfl_xor_sync(0xffffffffu, sm, o);
            sq += __shfl_xor_sync(0xffffffffu, sq, o);
        }
        if (tx == 0) {
            int o = ty * 8 + i;
            g_part[((size_t)o * GB + blockIdx.x) * 2]     = sm;
            g_part[((size_t)o * GB + blockIdx.x) * 2 + 1] = sq;
        }
    }

#pragma unroll
    for (int i = 0; i < 8; i++) {
        float mx = acc[i][0];
#pragma unroll
        for (int jj = 1; jj < 8; jj++) mx = fmaxf(mx, acc[i][jj]);
#pragma unroll
        for (int o = 4; o > 0; o >>= 1)
            mx = fmaxf(mx, __shfl_xor_sync(0xffffffffu, mx, o));
        if ((tx & 7) == 0) {
            int grp = (m0 >> 6) + (tx >> 3);
            g_max3[(size_t)(ty * 8 + i) * NG + grp] = mx;
        }
    }
}

// ---------------------------------------------------------------------------
// 5) BN stat finalize (layers 1-2) — one block per channel, fixed-order tree.
// ---------------------------------------------------------------------------
template<int LAYER>
__global__ void fin_par(const float* __restrict__ gam,
                        const float* __restrict__ bet)
{
    float* scl = (LAYER == 1) ? g_scl1 : g_scl2;
    float* shf = (LAYER == 1) ? g_shf1 : g_shf2;
    __shared__ float ssm[256], ssq[256];
    const int o = blockIdx.x;
    const int t = threadIdx.x;
    float sm = 0.f, sq = 0.f;
    const float* pp = g_part + (size_t)o * GB * 2;
    for (int i = t; i < GB; i += 256) {
        sm += pp[2 * i];
        sq += pp[2 * i + 1];
    }
    ssm[t] = sm; ssq[t] = sq;
    __syncthreads();
#pragma unroll
    for (int s2 = 128; s2 > 0; s2 >>= 1) {
        if (t < s2) { ssm[t] += ssm[t + s2]; ssq[t] += ssq[t + s2]; }
        __syncthreads();
    }
    if (t == 0) {
        float mean = ssm[0] * (1.0f / (float)M);
        float var  = ssq[0] * (1.0f / (float)M) - mean * mean;
        float sc = gam[o] * rsqrtf(var + 1e-5f);
        scl[o] = sc;
        shf[o] = fmaf(-mean, sc, bet[o]);
    }
}

// ---------------------------------------------------------------------------
// 6) Merged fin3 + output: one block per channel o.
// ---------------------------------------------------------------------------
__global__ void __launch_bounds__(256)
fin3_out_kernel(const float* __restrict__ gam, const float* __restrict__ bet,
                float* __restrict__ out)
{
    __shared__ float ssm[256], ssq[256];
    __shared__ float s_sc, s_sh;
    const int o = blockIdx.x;
    const int t = threadIdx.x;
    float sm = 0.f, sq = 0.f;
    const float* pp = g_part + (size_t)o * GB * 2;
    for (int i = t; i < GB; i += 256) {
        sm += pp[2 * i];
        sq += pp[2 * i + 1];
    }
    ssm[t] = sm; ssq[t] = sq;
    __syncthreads();
#pragma unroll
    for (int s2 = 128; s2 > 0; s2 >>= 1) {
        if (t < s2) { ssm[t] += ssm[t + s2]; ssq[t] += ssq[t + s2]; }
        __syncthreads();
    }
    if (t == 0) {
        float mean = ssm[0] * (1.0f / (float)M);
        float var  = ssq[0] * (1.0f / (float)M) - mean * mean;
        float sc = gam[o] * rsqrtf(var + 1e-5f);
        s_sc = sc;
        s_sh = fmaf(-mean, sc, bet[o]);
    }
    __syncthreads();
    float sc = s_sc, sh = s_sh;
    for (int g = t; g < NG; g += 256) {
        int b = g >> 10, s = g & 1023;
        float v = fmaxf(fmaf(g_max3[(size_t)o * NG + g], sc, sh), 0.f);
        out[OUT_FEAT + ((size_t)(b * 128 + o)) * S + s] = v;
    }
}

// ---------------------------------------------------------------------------
// Launch
// ---------------------------------------------------------------------------
extern "C" void kernel_launch(void* const* d_in, const int* in_sizes, int n_in,
                              void* d_out, int out_size)
{
    (void)in_sizes; (void)n_in; (void)out_size;
    const float* xyz  = (const float*)d_in[0];
    const float* feat = (const float*)d_in[1];
    const float* W1   = (const float*)d_in[2];
    const float* g1   = (const float*)d_in[3];
    const float* b1   = (const float*)d_in[4];
    const float* W2   = (const float*)d_in[5];
    const float* g2   = (const float*)d_in[6];
    const float* b2   = (const float*)d_in[7];
    const float* W3   = (const float*)d_in[8];
    const float* g3   = (const float*)d_in[9];
    const float* b3   = (const float*)d_in[10];
    float* out = (float*)d_out;

    cudaFuncSetAttribute(gemm_l2,
                         cudaFuncAttributeMaxDynamicSharedMemorySize, L2_SMEM);

    fps_kernel<<<B * CL, FPS_T>>>(xyz, out);
    ballgroup_kernel<<<(NG * 32) / 256, 256>>>(xyz, feat);

    gemm_p1<<<GB, 256>>>(W1);
    fin_par<1><<<64, 256>>>(g1, b1);

    gemm_l2<<<GB, 256, L2_SMEM>>>(W1, W2);
    fin_par<2><<<64, 256>>>(g2, b2);

    gemm128_l3<<<GB, 256>>>(W3);
    fin3_out_kernel<<<128, 256>>>(g3, b3, out);
}